// round 10
// baseline (speedup 1.0000x reference)
#include <cuda_runtime.h>
#include <cstdint>

// LGA: out[n,c,h,w] = sum_{i,j in 5x5} in1[n,c,h+i-2,w+j-2] * in2[n,i*5+j,h,w]
// Shapes fixed: in1 [4,32,384,768] f32, in2 [4,25,384,768] f32.
//
// Round-10: register-prefetched direct-global kernel. No smem, no barriers.
//  - 100 per-pixel taps (25 x float4) in registers, reused across 32 channels.
//  - Per row the thread's own float4 (M = d2..d5) is prefetched one full
//    channel ahead (5 x LDG.128 in flight); the halo pairs L/R (LDG.64) are
//    issued at use time and hit the L1 lines pulled in by the neighbors' M
//    prefetches. Removes all LDS reads, all LDGSTS smem writes, all barriers
//    (the round-7 L1-time ledger: 44us LDS + 21us smem-writes).
//  - Compute identical to round-7: packed fma.rn.f32x2 (exact f32 semantics).

#define NDIM 4
#define CDIM 32
#define HDIM 384
#define WDIM 768
#define KTAPS 25
#define PLANE (HDIM * WDIM)

#define BX 16
#define BY 8
#define NTHR (BX * BY)                // 128
#define TILE_W 64                     // 16 threads * 4 px
#define TILE_H 8

typedef unsigned long long u64;

__device__ __forceinline__ u64 pack2(float lo, float hi) {
    u64 r;
    asm("mov.b64 %0, {%1, %2};" : "=l"(r) : "f"(lo), "f"(hi));
    return r;
}
__device__ __forceinline__ void unpack2(u64 v, float& lo, float& hi) {
    asm("mov.b64 {%0, %1}, %2;" : "=f"(lo), "=f"(hi) : "l"(v));
}
__device__ __forceinline__ void fma2(u64& acc, u64 a, u64 b) {
    asm("fma.rn.f32x2 %0, %1, %2, %0;" : "+l"(acc) : "l"(a), "l"(b));
}

__global__ __launch_bounds__(NTHR, 3)
void lga_kernel(const float* __restrict__ in1,
                const float* __restrict__ in2,
                float* __restrict__ out) {
    const int tx = threadIdx.x;            // 0..15
    const int ty = threadIdx.y;            // 0..7
    const int wbase = blockIdx.x * TILE_W;
    const int hbase = blockIdx.y * TILE_H;
    const int n = blockIdx.z;

    const int h = hbase + ty;              // output row
    const int w0 = wbase + 4 * tx;         // first of 4 output cols (mult of 4)

    // ---- 25 per-pixel weight quads -> 50 packed f32x2 registers ----
    u64 w01[KTAPS], w23[KTAPS];
    {
        const float* wp = in2 + ((size_t)n * KTAPS * HDIM + h) * WDIM + w0;
#pragma unroll
        for (int t = 0; t < KTAPS; t++) {
            float4 v = __ldcs((const float4*)(wp + (size_t)t * PLANE));
            w01[t] = pack2(v.x, v.y);
            w23[t] = pack2(v.z, v.w);
        }
    }

    // ---- bounds predicates ----
    bool rowok[5];
#pragma unroll
    for (int i = 0; i < 5; i++) {
        int r = h - 2 + i;
        rowok[i] = (r >= 0) && (r < HDIM);
    }
    const bool vL = (w0 >= 2);             // cols w0-2,w0-1 in-bounds
    const bool vR = (w0 + 5 < WDIM);       // cols w0+4,w0+5 in-bounds

    // window base (row h-2, col w0) for channel 0
    const float* bp0 = in1 + (size_t)n * CDIM * PLANE + (size_t)(h - 2) * WDIM + w0;
    float* po = out + (size_t)n * CDIM * PLANE + (size_t)h * WDIM + w0;

    const float4 Z4 = make_float4(0.f, 0.f, 0.f, 0.f);
    const float2 Z2 = make_float2(0.f, 0.f);

    // ---- prefetch channel 0 center vectors ----
    float4 Ma[5], Mb[5];
#pragma unroll
    for (int i = 0; i < 5; i++)
        Ma[i] = rowok[i] ? *(const float4*)(bp0 + i * WDIM) : Z4;

    // one channel: consume Mc (prefetched), prefetch channel c+1 into Mn
#define DO_CHANNEL(c, Mc, Mn)                                                  \
    {                                                                          \
        const float* bp = bp0 + (size_t)(c) * PLANE;                           \
        if ((c) + 1 < CDIM) {                                                  \
            const float* np = bp + PLANE;                                      \
            _Pragma("unroll")                                                  \
            for (int i = 0; i < 5; i++)                                        \
                Mn[i] = rowok[i] ? *(const float4*)(np + i * WDIM) : Z4;       \
        }                                                                      \
        u64 acc01 = 0, acc23 = 0;                                              \
        _Pragma("unroll")                                                      \
        for (int i = 0; i < 5; i++) {                                          \
            float2 L = (vL && rowok[i]) ? *(const float2*)(bp + i * WDIM - 2)  \
                                        : Z2;                                  \
            float2 R = (vR && rowok[i]) ? *(const float2*)(bp + i * WDIM + 4)  \
                                        : Z2;                                  \
            float4 M = Mc[i];                                                  \
            u64 p01 = pack2(L.x, L.y);                                         \
            u64 p12 = pack2(L.y, M.x);                                         \
            u64 p23 = pack2(M.x, M.y);                                         \
            u64 p34 = pack2(M.y, M.z);                                         \
            u64 p45 = pack2(M.z, M.w);                                         \
            u64 p56 = pack2(M.w, R.x);                                         \
            u64 p67 = pack2(R.x, R.y);                                         \
            const u64* wr01 = &w01[5 * i];                                     \
            const u64* wr23 = &w23[5 * i];                                     \
            fma2(acc01, p01, wr01[0]);                                         \
            fma2(acc23, p23, wr23[0]);                                         \
            fma2(acc01, p12, wr01[1]);                                         \
            fma2(acc23, p34, wr23[1]);                                         \
            fma2(acc01, p23, wr01[2]);                                         \
            fma2(acc23, p45, wr23[2]);                                         \
            fma2(acc01, p34, wr01[3]);                                         \
            fma2(acc23, p56, wr23[3]);                                         \
            fma2(acc01, p45, wr01[4]);                                         \
            fma2(acc23, p67, wr23[4]);                                         \
        }                                                                      \
        float4 o;                                                              \
        unpack2(acc01, o.x, o.y);                                              \
        unpack2(acc23, o.z, o.w);                                              \
        __stcs((float4*)(po + (size_t)(c) * PLANE), o);                        \
    }

#pragma unroll 1
    for (int c = 0; c < CDIM; c += 2) {
        DO_CHANNEL(c,     Ma, Mb);
        DO_CHANNEL(c + 1, Mb, Ma);
    }
#undef DO_CHANNEL
}

extern "C" void kernel_launch(void* const* d_in, const int* in_sizes, int n_in,
                              void* d_out, int out_size) {
    const float* in1 = (const float*)d_in[0];
    const float* in2 = (const float*)d_in[1];
    float* out = (float*)d_out;

    dim3 block(BX, BY);
    dim3 grid(WDIM / TILE_W, HDIM / TILE_H, NDIM);  // 12 x 48 x 4
    lga_kernel<<<grid, block>>>(in1, in2, out);
}

// round 11
// speedup vs baseline: 2.1534x; 2.1534x over previous
#include <cuda_runtime.h>
#include <cstdint>

// LGA: out[n,c,h,w] = sum_{i,j in 5x5} in1[n,c,h+i-2,w+j-2] * in2[n,i*5+j,h,w]
// Shapes fixed: in1 [4,32,384,768] f32, in2 [4,25,384,768] f32.
//
// Round-11 = round-7 pipeline + BANK-CONFLICT-FREE staging.
//  - SPITCH=74 (pitch == 2 mod 4): the two 16-lane halves of a warp (ty, ty+1)
//    land on complementary bank sets, so every stride-4 LDS.64 is exactly 2
//    wavefronts (the minimum). Row window read = 4x LDS.64 = 8 wavefronts
//    vs round-7's 12 (its f2 loads were 4-way bank conflicted).
//  - cp.async staging: even stage rows 18x16B chunks (.cg); odd rows are only
//    8B-aligned in smem -> 36x8B chunks (.ca). Zero-fill at borders.
//  - Compute/pipeline otherwise identical to round 7 (best: 92.9us).

#define NDIM 4
#define CDIM 32
#define HDIM 384
#define WDIM 768
#define KTAPS 25
#define PLANE (HDIM * WDIM)

#define BX 16
#define BY 8
#define NTHR (BX * BY)                // 128
#define TILE_W 64                     // 16 threads * 4 px
#define TILE_H 8
#define SROWS (TILE_H + 4)            // 12
#define SPITCH 74                     // floats per smem row; 74 % 4 == 2
#define STAGE_ELEMS (SROWS * SPITCH)  // 888
#define STAGES 4                      // ring of channel PAIRS
#define NPAIR (CDIM / 2)              // 16
// copy ops per channel: 6 even rows x 18 cp16 + 6 odd rows x 36 cp8
#define N16 108
#define N8  216

typedef unsigned long long u64;

__device__ __forceinline__ uint32_t smem_u32(const void* p) {
    return (uint32_t)__cvta_generic_to_shared(p);
}
__device__ __forceinline__ void cp_async16(uint32_t dst, const float* src, int sz) {
    asm volatile("cp.async.cg.shared.global [%0], [%1], 16, %2;\n"
                 :: "r"(dst), "l"(src), "r"(sz));
}
__device__ __forceinline__ void cp_async8(uint32_t dst, const float* src, int sz) {
    asm volatile("cp.async.ca.shared.global [%0], [%1], 8, %2;\n"
                 :: "r"(dst), "l"(src), "r"(sz));
}
__device__ __forceinline__ void cp_commit() {
    asm volatile("cp.async.commit_group;\n" ::: "memory");
}
__device__ __forceinline__ void cp_wait2() {
    asm volatile("cp.async.wait_group 2;\n" ::: "memory");
}
__device__ __forceinline__ u64 pack2(float lo, float hi) {
    u64 r;
    asm("mov.b64 %0, {%1, %2};" : "=l"(r) : "f"(lo), "f"(hi));
    return r;
}
__device__ __forceinline__ void unpack2(u64 v, float& lo, float& hi) {
    asm("mov.b64 {%0, %1}, %2;" : "=f"(lo), "=f"(hi) : "l"(v));
}
__device__ __forceinline__ void fma2(u64& acc, u64 a, u64 b) {
    asm("fma.rn.f32x2 %0, %1, %2, %0;" : "+l"(acc) : "l"(a), "l"(b));
}

__global__ __launch_bounds__(NTHR, 3)
void lga_kernel(const float* __restrict__ in1,
                const float* __restrict__ in2,
                float* __restrict__ out) {
    __shared__ __align__(16) float ring[STAGES][2][STAGE_ELEMS];

    const int tx = threadIdx.x;            // 0..15
    const int ty = threadIdx.y;            // 0..7
    const int tid = ty * BX + tx;
    const int wbase = blockIdx.x * TILE_W;
    const int hbase = blockIdx.y * TILE_H;
    const int n = blockIdx.z;

    const int h = hbase + ty;              // output row
    const int w0 = wbase + 4 * tx;         // first of 4 output cols

    // ---- 25 per-pixel weight quads -> 50 packed f32x2 registers ----
    u64 w01[KTAPS], w23[KTAPS];
    {
        const float* wp = in2 + ((size_t)n * KTAPS * HDIM + h) * WDIM + w0;
#pragma unroll
        for (int t = 0; t < KTAPS; t++) {
            float4 v = __ldcs((const float4*)(wp + (size_t)t * PLANE));
            w01[t] = pack2(v.x, v.y);
            w23[t] = pack2(v.z, v.w);
        }
    }

    // ---- copy roles (3 slots) ----
    // slot0: tid <  N16 : cp16 op #tid        (even rows)
    // slot1: all        : cp8  op #tid        (odd rows, ids 0..127)
    // slot2: tid <  88  : cp8  op #(tid+128)  (odd rows, ids 128..215)
    const float* in1n = in1 + (size_t)n * CDIM * PLANE;
    int g16 = 0, sz16 = 0, s16 = 0;
    int g8a = 0, sz8a = 0, s8a = 0;
    int g8b = 0, sz8b = 0, s8b = 0;
    const bool has16 = (tid < N16);
    const bool has8b = (tid < N8 - NTHR);  // 88
    {
        if (has16) {
            int r  = 2 * (tid / 18);
            int ch = tid % 18;
            int gy = hbase - 2 + r, gx0 = wbase - 4 + 4 * ch;
            bool v = (gy >= 0) && (gy < HDIM) && (gx0 >= 0) && (gx0 + 3 < WDIM);
            g16 = v ? (gy * WDIM + gx0) : 0;
            sz16 = v ? 16 : 0;
            s16 = r * SPITCH + 4 * ch;
        }
        {   // slot1
            int k = tid;
            int r  = 2 * (k / 36) + 1;
            int ch = k % 36;
            int gy = hbase - 2 + r, gx0 = wbase - 4 + 2 * ch;
            bool v = (gy >= 0) && (gy < HDIM) && (gx0 >= 0) && (gx0 + 1 < WDIM);
            g8a = v ? (gy * WDIM + gx0) : 0;
            sz8a = v ? 8 : 0;
            s8a = r * SPITCH + 2 * ch;
        }
        if (has8b) {
            int k = tid + NTHR;
            int r  = 2 * (k / 36) + 1;
            int ch = k % 36;
            int gy = hbase - 2 + r, gx0 = wbase - 4 + 2 * ch;
            bool v = (gy >= 0) && (gy < HDIM) && (gx0 >= 0) && (gx0 + 1 < WDIM);
            g8b = v ? (gy * WDIM + gx0) : 0;
            sz8b = v ? 8 : 0;
            s8b = r * SPITCH + 2 * ch;
        }
    }

    float* po = out + (size_t)n * CDIM * PLANE + (size_t)h * WDIM + w0;

    uint32_t sbase[STAGES][2];
#pragma unroll
    for (int s = 0; s < STAGES; s++) {
        sbase[s][0] = smem_u32(&ring[s][0][0]);
        sbase[s][1] = smem_u32(&ring[s][1][0]);
    }

    // issue the copy of channel pair p into stage s (one commit group)
    auto issue = [&](int p, int s) {
#pragma unroll
        for (int half = 0; half < 2; half++) {
            const float* src = in1n + (size_t)(2 * p + half) * PLANE;
            uint32_t d = sbase[s][half];
            if (has16) cp_async16(d + 4 * s16, src + g16, sz16);
            cp_async8(d + 4 * s8a, src + g8a, sz8a);
            if (has8b) cp_async8(d + 4 * s8b, src + g8b, sz8b);
        }
        cp_commit();
    };

    // ---- prologue: pairs 0..2 (channels 0..5) in flight ----
    issue(0, 0);
    issue(1, 1);
    issue(2, 2);

#pragma unroll 1
    for (int p = 0; p < NPAIR; p++) {
        const int s = p & (STAGES - 1);

        cp_wait2();
        __syncthreads();

        if (p + 3 < NPAIR) issue(p + 3, (p + 3) & (STAGES - 1));
        else               cp_commit();

#pragma unroll
        for (int half = 0; half < 2; half++) {
            // staged col0 = wbase-4; window d0 = col w0-2 -> 4*tx+2
            const float* basep = &ring[s][half][ty * SPITCH + 4 * tx + 2];
            u64 acc01 = 0, acc23 = 0;
#pragma unroll
            for (int i = 0; i < 5; i++) {
                const float* rp = basep + i * SPITCH;
                float2 A0 = *(const float2*)(rp + 0);   // d0 d1
                float2 A1 = *(const float2*)(rp + 2);   // d2 d3
                float2 A2 = *(const float2*)(rp + 4);   // d4 d5
                float2 A3 = *(const float2*)(rp + 6);   // d6 d7

                u64 p01 = pack2(A0.x, A0.y);
                u64 p12 = pack2(A0.y, A1.x);
                u64 p23 = pack2(A1.x, A1.y);
                u64 p34 = pack2(A1.y, A2.x);
                u64 p45 = pack2(A2.x, A2.y);
                u64 p56 = pack2(A2.y, A3.x);
                u64 p67 = pack2(A3.x, A3.y);

                const u64* wr01 = &w01[5 * i];
                const u64* wr23 = &w23[5 * i];
                fma2(acc01, p01, wr01[0]);
                fma2(acc23, p23, wr23[0]);
                fma2(acc01, p12, wr01[1]);
                fma2(acc23, p34, wr23[1]);
                fma2(acc01, p23, wr01[2]);
                fma2(acc23, p45, wr23[2]);
                fma2(acc01, p34, wr01[3]);
                fma2(acc23, p56, wr23[3]);
                fma2(acc01, p45, wr01[4]);
                fma2(acc23, p67, wr23[4]);
            }
            float4 o;
            unpack2(acc01, o.x, o.y);
            unpack2(acc23, o.z, o.w);
            __stcs((float4*)(po + (size_t)(2 * p + half) * PLANE), o);
        }
    }
}

extern "C" void kernel_launch(void* const* d_in, const int* in_sizes, int n_in,
                              void* d_out, int out_size) {
    const float* in1 = (const float*)d_in[0];
    const float* in2 = (const float*)d_in[1];
    float* out = (float*)d_out;

    dim3 block(BX, BY);
    dim3 grid(WDIM / TILE_W, HDIM / TILE_H, NDIM);  // 12 x 48 x 4
    lga_kernel<<<grid, block>>>(in1, in2, out);
}